// round 14
// baseline (speedup 1.0000x reference)
#include <cuda_runtime.h>
#include <cuda_fp16.h>
#include <cstdint>
#include <math.h>

#define Bz 8
#define Sz 1024
#define Dz 512
#define Hz 8
#define DHz 64
#define FFz 2048
#define Lz 4
#define Nz (Bz*Sz)

typedef __half hf;
typedef __half2 hf2;

static constexpr size_t NB = (size_t)Nz*Dz;
static constexpr size_t FBsz = (size_t)Nz*FFz;
static constexpr size_t WPROJ = (size_t)Lz*Dz*Dz;
static constexpr size_t WFF = (size_t)Lz*Dz*FFz;

static constexpr size_t XBUF=0, TBUF=NB, YBUF=2*NB,
  QHo=3*NB, KHo=QHo+NB/2, VTHo=KHo+NB/2, ABHo=VTHo+NB/2,
  XHo=ABHo+NB/2, YHo=XHo+NB/2, FHo=YHo+NB/2,
  WQo=FHo+FBsz/2, WKo=WQo+WPROJ/2, WVo=WKo+WPROJ/2, WOo=WVo+WPROJ/2,
  W1o=WOo+WPROJ/2, W2o=W1o+WFF/2, SCRATCH_TOTAL=W2o+WFF/2;

__device__ float g_scratch[SCRATCH_TOTAL];

__device__ __forceinline__ uint32_t smem_u32(const void* p){ return (uint32_t)__cvta_generic_to_shared(p); }
__device__ __forceinline__ uint32_t pack2h(float a, float b){
  hf2 t = __floats2half2_rn(a,b); uint32_t r; memcpy(&r,&t,4); return r; }

__device__ __forceinline__ void cp16(uint32_t d,const void* s){
  asm volatile("cp.async.cg.shared.global [%0],[%1],16;"::"r"(d),"l"(s):"memory"); }
#define CP_COMMIT() asm volatile("cp.async.commit_group;":::"memory")
#define CP_WAIT(n) asm volatile("cp.async.wait_group %0;"::"n"(n):"memory")

#define LDSM4(r,addr) asm volatile("ldmatrix.sync.aligned.m8n8.x4.shared.b16 {%0,%1,%2,%3},[%4];" \
  :"=r"((r)[0]),"=r"((r)[1]),"=r"((r)[2]),"=r"((r)[3]):"r"(addr))

#define MMA_F16(c,a,b) asm volatile( \
  "mma.sync.aligned.m16n8k16.row.col.f32.f16.f16.f32 {%0,%1,%2,%3},{%4,%5,%6,%7},{%8,%9},{%0,%1,%2,%3};" \
  : "+f"((c)[0]),"+f"((c)[1]),"+f"((c)[2]),"+f"((c)[3]) \
  : "r"((a)[0]),"r"((a)[1]),"r"((a)[2]),"r"((a)[3]),"r"((b)[0]),"r"((b)[1]))

// GEMM: CTA 256x128, warp 64x64 (4x2 warps), K-chunk 32, stage 24KB x3 = 72KB
#define A_TILE_H 16384
#define STAGE_H 24576
static constexpr uint32_t GEMM_SMEM = 3*STAGE_H;

__device__ __forceinline__ uint32_t swz64(int r, int kby){
  return (uint32_t)(r*64 + ((((kby>>4) ^ ((r>>1)&3)))<<4));
}

__device__ __forceinline__ void gemm_core(uint32_t sbase,
  const hf* bA, const hf* bB, int K, float (&acc)[4][8][4])
{
  int tid=threadIdx.x, wid=tid>>5, lane=tid&31;
  int KT = K>>5;

  auto load_chunk=[&](int kt,int s){
    uint32_t sb = sbase + (uint32_t)s*STAGE_H;
    int k0e = kt<<5;
    #pragma unroll
    for(int i=0;i<4;i++){            // A: 256 rows x 64B
      int u = (i<<8) + tid;
      int r = u>>2, c = u&3;
      cp16(sb + swz64(r, c<<4), bA + (size_t)r*K + k0e + c*8);
    }
    #pragma unroll
    for(int i=0;i<2;i++){            // B: 128 rows x 64B
      int u = (i<<8) + tid;
      int r = u>>2, c = u&3;
      cp16(sb + A_TILE_H + swz64(r, c<<4), bB + (size_t)r*K + k0e + c*8);
    }
  };

  int wm = wid>>1, wn = wid&1;
  int mA = wm*64 + (lane&7) + ((lane>>3)&1)*8;
  int kAby = ((lane>>4)&1)*16;
  int nB0 = wn*64 + (lane&7) + ((lane>>4)&1)*8;
  int kBby = ((lane>>3)&1)*16;

  load_chunk(0,0); CP_COMMIT();
  load_chunk(1,1); CP_COMMIT();

  for(int kt=0;kt<KT;kt++){
    if(kt+1<KT){ CP_WAIT(1); } else { CP_WAIT(0); }
    __syncthreads();
    if(kt+2<KT){ load_chunk(kt+2,(kt+2)%3); CP_COMMIT(); }
    uint32_t sb = sbase + (uint32_t)(kt%3)*STAGE_H;
    uint32_t sA=sb, sB=sb+A_TILE_H;
    #pragma unroll
    for(int st=0; st<2; st++){
      int kby0 = st*32;
      uint32_t af[16];
      #pragma unroll
      for(int mt=0;mt<4;mt++){
        int r = mA + mt*16;
        LDSM4(&af[mt*4], sA + swz64(r, kby0+kAby));
      }
      #pragma unroll
      for(int hv=0; hv<2; hv++){
        uint32_t bfr[8];
        #pragma unroll
        for(int bt=0;bt<2;bt++){
          int n = nB0 + (hv*2+bt)*16;
          LDSM4(&bfr[bt*4], sB + swz64(n, kby0+kBby));
        }
        #pragma unroll
        for(int mt=0;mt<4;mt++)
          #pragma unroll
          for(int nt=0;nt<4;nt++)
            MMA_F16(acc[mt][hv*4+nt], &af[mt*4], &bfr[(nt>>1)*4 + (nt&1)*2]);
      }
    }
  }
}

__device__ __forceinline__ void epi_f32(float (&acc)[4][8][4], const float* bias,
  float* C, int row0, int col0, int M, int wm, int wn, int lane)
{
  #pragma unroll
  for(int mt=0;mt<4;mt++){
    int r0 = row0 + wm*64 + mt*16 + (lane>>2);
    #pragma unroll
    for(int nt=0;nt<8;nt++){
      int c0i = col0 + wn*64 + nt*8 + 2*(lane&3);
      float b0v=bias[c0i], b1v=bias[c0i+1];
      float* a = acc[mt][nt];
      *(float2*)&C[(size_t)r0*M + c0i]     = make_float2(a[0]+b0v, a[1]+b1v);
      *(float2*)&C[(size_t)(r0+8)*M + c0i] = make_float2(a[2]+b0v, a[3]+b1v);
    }
  }
}

template<bool RELU>
__device__ __forceinline__ void epi_h(float (&acc)[4][8][4], const float* bias,
  hf* C, int row0, int col0, int M, int wm, int wn, int lane)
{
  #pragma unroll
  for(int mt=0;mt<4;mt++){
    int r0 = row0 + wm*64 + mt*16 + (lane>>2);
    #pragma unroll
    for(int nt=0;nt<8;nt++){
      int c0i = col0 + wn*64 + nt*8 + 2*(lane&3);
      float b0v=bias[c0i], b1v=bias[c0i+1];
      float* a = acc[mt][nt];
      float v00=a[0]+b0v, v01=a[1]+b1v, v10=a[2]+b0v, v11=a[3]+b1v;
      if(RELU){ v00=fmaxf(v00,0.f); v01=fmaxf(v01,0.f); v10=fmaxf(v10,0.f); v11=fmaxf(v11,0.f); }
      *(hf2*)&C[(size_t)r0*M + c0i]     = __floats2half2_rn(v00,v01);
      *(hf2*)&C[(size_t)(r0+8)*M + c0i] = __floats2half2_rn(v10,v11);
    }
  }
}

__device__ __forceinline__ void epi_vt(float (&acc)[4][8][4], const float* bias,
  hf* C, int row0, int col0, int wm, int wn, int lane)
{
  #pragma unroll
  for(int mt=0;mt<4;mt++){
    int r0 = row0 + wm*64 + mt*16 + (lane>>2);
    #pragma unroll
    for(int nt=0;nt<8;nt++){
      int c0i = col0 + wn*64 + nt*8 + 2*(lane&3);
      float b0v=bias[c0i], b1v=bias[c0i+1];
      float* a = acc[mt][nt];
      float v00=a[0]+b0v, v01=a[1]+b1v, v10=a[2]+b0v, v11=a[3]+b1v;
      int bI=r0>>10, sI=r0&1023, hI=c0i>>6, dI=c0i&63;
      size_t db = ((size_t)bI*Hz + hI)*DHz;
      C[(db+dI)*Sz+sI]   = __float2half_rn(v00);
      C[(db+dI+1)*Sz+sI] = __float2half_rn(v01);
      C[(db+dI)*Sz+sI+8]   = __float2half_rn(v10);
      C[(db+dI+1)*Sz+sI+8] = __float2half_rn(v11);
    }
  }
}

#define ACC_INIT(acc) { \
  _Pragma("unroll") \
  for(int mt=0;mt<4;mt++) \
    _Pragma("unroll") \
    for(int nt=0;nt<8;nt++){ acc[mt][nt][0]=0.f;acc[mt][nt][1]=0.f;acc[mt][nt][2]=0.f;acc[mt][nt][3]=0.f; } }

// MODE 0: fp32 out, 1: relu+half, 2: half
template<int MODE>
__global__ __launch_bounds__(256,1) void gemm_std_kernel(
  const hf* __restrict__ A, const hf* __restrict__ B,
  const float* __restrict__ bias, float* __restrict__ C,
  hf* __restrict__ Ch, int K, int M)
{
  extern __shared__ char smem[];
  uint32_t sbase = smem_u32(smem);
  int row0=blockIdx.y*256, col0=blockIdx.x*128;
  float acc[4][8][4];
  ACC_INIT(acc)
  gemm_core(sbase, A+(size_t)row0*K, B+(size_t)col0*K, K, acc);
  int wid=threadIdx.x>>5, lane=threadIdx.x&31;
  int wm=wid>>1, wn=wid&1;
  if(MODE==0) epi_f32(acc,bias,C,row0,col0,M,wm,wn,lane);
  else if(MODE==1) epi_h<true>(acc,bias,Ch,row0,col0,M,wm,wn,lane);
  else epi_h<false>(acc,bias,Ch,row0,col0,M,wm,wn,lane);
}

// merged QKV: blockIdx.x 0-3 Q, 4-7 K, 8-11 V(transpose); rows 256/CTA
__global__ __launch_bounds__(256,1) void gemm_qkv_kernel(
  const hf* __restrict__ A,
  const hf* __restrict__ Wq, const hf* __restrict__ Wk, const hf* __restrict__ Wv,
  const float* __restrict__ bq, const float* __restrict__ bk, const float* __restrict__ bv,
  hf* __restrict__ Qh, hf* __restrict__ Kh, hf* __restrict__ Vth)
{
  extern __shared__ char smem[];
  uint32_t sbase = smem_u32(smem);
  int sel = blockIdx.x>>2;
  int row0=blockIdx.y*256, col0=(blockIdx.x&3)*128;
  const hf* B = (sel==0)?Wq:(sel==1)?Wk:Wv;
  const float* bias = (sel==0)?bq:(sel==1)?bk:bv;
  float acc[4][8][4];
  ACC_INIT(acc)
  gemm_core(sbase, A+(size_t)row0*Dz, B+(size_t)col0*Dz, Dz, acc);
  int wid=threadIdx.x>>5, lane=threadIdx.x&31;
  int wm=wid>>1, wn=wid&1;
  if(sel==0) epi_h<false>(acc,bias,Qh,row0,col0,Dz,wm,wn,lane);
  else if(sel==1) epi_h<false>(acc,bias,Kh,row0,col0,Dz,wm,wn,lane);
  else epi_vt(acc,bias,Vth,row0,col0,wm,wn,lane);
}

// -------------------- fused flash attention (unchanged from R13) --------------------
static constexpr uint32_t FLASH_SMEM = 16384 + 2*32768;

__global__ __launch_bounds__(256,2) void flash_kernel(
  const hf* __restrict__ Q, const hf* __restrict__ Km,
  const hf* __restrict__ Vt, const int* __restrict__ lens,
  hf* __restrict__ O)
{
  extern __shared__ char smem[];
  uint32_t sb = smem_u32(smem);
  uint32_t sQ=sb;
  int tid=threadIdx.x, wid=tid>>5, lane=tid&31;
  int bh=blockIdx.y, b=bh>>3, h=bh&7;
  int q0=blockIdx.x*128;
  int len = lens[b];
  int ntiles = (len+127)>>7;

  size_t qrow = ((size_t)b*Sz+q0)*Dz + h*DHz;
  for(int u=tid; u<1024; u+=256){
    int r=u>>3, c=u&7;
    uint32_t off=(uint32_t)(r*128 + ((c*16) ^ ((r&7)*16)));
    cp16(sQ+off, Q+qrow+(size_t)r*Dz+c*8);
  }
  auto load_kv=[&](int kt,int stg){
    uint32_t s0 = sb + 16384 + (uint32_t)stg*32768;
    int k0 = kt<<7;
    size_t krow = ((size_t)b*Sz+k0)*Dz + h*DHz;
    for(int u=tid; u<1024; u+=256){
      int r=u>>3, c=u&7;
      uint32_t off=(uint32_t)(r*128 + ((c*16) ^ ((r&7)*16)));
      cp16(s0+off, Km+krow+(size_t)r*Dz+c*8);
    }
    size_t vrow = (size_t)bh*DHz*Sz + k0;
    for(int u=tid; u<1024; u+=256){
      int r=u>>4, c=u&15;
      uint32_t off=(uint32_t)(r*256 + ((c*16) ^ ((r&7)*16)));
      cp16(s0+16384+off, Vt+vrow+(size_t)r*Sz+c*8);
    }
  };
  load_kv(0,0);
  CP_COMMIT();

  float mrow0=-1e30f, mrow1=-1e30f, lrow0=0.f, lrow1=0.f;
  float oacc[8][4];
  #pragma unroll
  for(int i=0;i<8;i++){
    #pragma unroll
    for(int j=0;j<4;j++) oacc[i][j]=0.f; }

  int rA = wid*16 + (lane&7) + ((lane>>3)&1)*8;
  int kAby = ((lane>>4)&1)*16;
  int nBb = (lane&7) + ((lane>>4)&1)*8;
  int kBby = ((lane>>3)&1)*16;
  uint32_t offaQ[4];
  #pragma unroll
  for(int st=0;st<4;st++)
    offaQ[st]=(uint32_t)(rA*128 + ((st*32+kAby) ^ ((rA&7)*16)));

  for(int kt=0;kt<ntiles;kt++){
    CP_WAIT(0);
    __syncthreads();
    if(kt+1<ntiles){ load_kv(kt+1,(kt+1)&1); CP_COMMIT(); }
    uint32_t s0 = sb + 16384 + (uint32_t)(kt&1)*32768;
    uint32_t sK=s0, sV=s0+16384;

    float sacc[16][4];
    #pragma unroll
    for(int i=0;i<16;i++){
      #pragma unroll
      for(int j=0;j<4;j++) sacc[i][j]=0.f; }

    #pragma unroll
    for(int st=0;st<4;st++){
      uint32_t af[4];
      LDSM4(af, sQ+offaQ[st]);
      #pragma unroll
      for(int g=0;g<8;g++){
        int n = g*16 + nBb;
        uint32_t offb=(uint32_t)(n*128 + ((st*32+kBby) ^ ((n&7)*16)));
        uint32_t bfr[4];
        LDSM4(bfr, sK+offb);
        MMA_F16(sacc[2*g],   af, &bfr[0]);
        MMA_F16(sacc[2*g+1], af, &bfr[2]);
      }
    }

    int k0 = kt<<7;
    bool need_mask = (k0+128 > len);
    #pragma unroll
    for(int nt=0;nt<16;nt++){
      #pragma unroll
      for(int j=0;j<4;j++){
        float s = sacc[nt][j]*0.125f;
        if(need_mask){
          int col = k0 + nt*8 + 2*(lane&3) + (j&1);
          if(col>=len) s=-1e30f;
        }
        sacc[nt][j]=s;
      }
    }
    float mx0=-1e30f, mx1=-1e30f;
    #pragma unroll
    for(int nt=0;nt<16;nt++){
      mx0=fmaxf(mx0,fmaxf(sacc[nt][0],sacc[nt][1]));
      mx1=fmaxf(mx1,fmaxf(sacc[nt][2],sacc[nt][3]));
    }
    mx0=fmaxf(mx0,__shfl_xor_sync(0xffffffffu,mx0,1));
    mx0=fmaxf(mx0,__shfl_xor_sync(0xffffffffu,mx0,2));
    mx1=fmaxf(mx1,__shfl_xor_sync(0xffffffffu,mx1,1));
    mx1=fmaxf(mx1,__shfl_xor_sync(0xffffffffu,mx1,2));
    float mn0=fmaxf(mrow0,mx0), mn1=fmaxf(mrow1,mx1);
    float sc0=__expf(mrow0-mn0), sc1=__expf(mrow1-mn1);
    mrow0=mn0; mrow1=mn1;
    float sum0=0.f, sum1=0.f;
    #pragma unroll
    for(int nt=0;nt<16;nt++){
      float p0=__expf(sacc[nt][0]-mn0), p1=__expf(sacc[nt][1]-mn0);
      float p2=__expf(sacc[nt][2]-mn1), p3=__expf(sacc[nt][3]-mn1);
      sacc[nt][0]=p0; sacc[nt][1]=p1; sacc[nt][2]=p2; sacc[nt][3]=p3;
      sum0+=p0+p1; sum1+=p2+p3;
    }
    sum0+=__shfl_xor_sync(0xffffffffu,sum0,1);
    sum0+=__shfl_xor_sync(0xffffffffu,sum0,2);
    sum1+=__shfl_xor_sync(0xffffffffu,sum1,1);
    sum1+=__shfl_xor_sync(0xffffffffu,sum1,2);
    lrow0=lrow0*sc0+sum0; lrow1=lrow1*sc1+sum1;
    #pragma unroll
    for(int nt=0;nt<8;nt++){
      oacc[nt][0]*=sc0; oacc[nt][1]*=sc0; oacc[nt][2]*=sc1; oacc[nt][3]*=sc1;
    }

    #pragma unroll
    for(int j=0;j<8;j++){
      uint32_t pa[4];
      pa[0]=pack2h(sacc[2*j][0],  sacc[2*j][1]);
      pa[1]=pack2h(sacc[2*j][2],  sacc[2*j][3]);
      pa[2]=pack2h(sacc[2*j+1][0],sacc[2*j+1][1]);
      pa[3]=pack2h(sacc[2*j+1][2],sacc[2*j+1][3]);
      #pragma unroll
      for(int g=0;g<4;g++){
        int n = g*16 + nBb;
        uint32_t offv=(uint32_t)(n*256 + ((j*32+kBby) ^ ((n&7)*16)));
        uint32_t vf[4];
        LDSM4(vf, sV+offv);
        MMA_F16(oacc[2*g],   pa, &vf[0]);
        MMA_F16(oacc[2*g+1], pa, &vf[2]);
      }
    }
  }

  float li0=1.f/lrow0, li1=1.f/lrow1;
  int r0 = q0 + wid*16 + (lane>>2);
  #pragma unroll
  for(int nt=0;nt<8;nt++){
    int c = h*64 + nt*8 + 2*(lane&3);
    size_t o0 = ((size_t)b*Sz+r0)*Dz + c;
    size_t o1 = o0 + (size_t)8*Dz;
    *(hf2*)&O[o0] = __floats2half2_rn(oacc[nt][0]*li0, oacc[nt][1]*li0);
    *(hf2*)&O[o1] = __floats2half2_rn(oacc[nt][2]*li1, oacc[nt][3]*li1);
  }
}

// -------------------- small kernels --------------------
__device__ __forceinline__ void wsplit_body(const float* Wz, hf* th,
  int K, int M, int m0, int k0, size_t zo)
{
  __shared__ float t[32][33];
  int tx=threadIdx.x, ty=threadIdx.y;
  #pragma unroll
  for(int j=0;j<4;j++) t[ty+8*j][tx] = Wz[(size_t)(k0+ty+8*j)*M + m0+tx];
  __syncthreads();
  #pragma unroll
  for(int j=0;j<4;j++){
    size_t o = zo + (size_t)(m0+ty+8*j)*K + k0+tx;
    th[o] = __float2half_rn(t[tx][ty+8*j]);
  }
}

__global__ __launch_bounds__(256) void wsplit_proj_kernel(
  const float* __restrict__ Wq, const float* __restrict__ Wk,
  const float* __restrict__ Wv, const float* __restrict__ Wo,
  hf* qh, hf* kh, hf* vh, hf* oh)
{
  int w = blockIdx.z & 3, l = blockIdx.z >> 2;
  const float* W; hf* th;
  switch(w){
    case 0: W=Wq; th=qh; break;
    case 1: W=Wk; th=kh; break;
    case 2: W=Wv; th=vh; break;
    default: W=Wo; th=oh; break;
  }
  size_t zo = (size_t)l*Dz*Dz;
  wsplit_body(W+zo, th, Dz, Dz, blockIdx.x*32, blockIdx.y*32, zo);
}

__global__ __launch_bounds__(256) void wsplit_ff_kernel(
  const float* __restrict__ W1, const float* __restrict__ W2,
  hf* h1, hf* h2)
{
  int which = blockIdx.z>>2, l = blockIdx.z&3;
  size_t zo = (size_t)l*Dz*FFz;
  if(which==0)
    wsplit_body(W1+zo, h1, Dz, FFz, blockIdx.x*32, blockIdx.y*32, zo);
  else
    wsplit_body(W2+zo, h2, FFz, Dz, blockIdx.y*32, blockIdx.x*32, zo);
}

__global__ __launch_bounds__(256) void posenc_kernel(const float* __restrict__ x,
  float* __restrict__ out, hf* __restrict__ oh)
{
  int idx = blockIdx.x*256 + threadIdx.x;
  int d = idx & (Dz-1), s = (idx>>9) & (Sz-1);
  int i2 = d & ~1;
  float divv = (float)exp((double)i2 * (-9.210340371976184/(double)Dz));
  float ang = (float)s * divv;
  float pe = (d&1) ? cosf(ang) : sinf(ang);
  float v = x[idx] + pe;
  out[idx] = v;
  oh[idx] = __float2half_rn(v);
}

template<bool WH>
__global__ __launch_bounds__(256) void ln_kernel(
  const float* __restrict__ Xa, const float* __restrict__ Xb,
  const float* __restrict__ g, const float* __restrict__ be,
  float* __restrict__ out, hf* __restrict__ oh)
{
  int n=blockIdx.x;
  const float* a = Xa + (size_t)n*Dz;
  const float* c = Xb + (size_t)n*Dz;
  int tid=threadIdx.x, lane=tid&31, w=tid>>5;
  __shared__ float sh[8];
  float s0=a[tid]+c[tid], s1=a[tid+256]+c[tid+256];
  float sum=s0+s1;
  #pragma unroll
  for(int o=16;o;o>>=1) sum+=__shfl_xor_sync(0xffffffffu,sum,o);
  if(lane==0) sh[w]=sum;
  __syncthreads();
  float tot=0.f;
  #pragma unroll
  for(int i=0;i<8;i++) tot+=sh[i];
  __syncthreads();
  float mean=tot*(1.0f/(float)Dz);
  float d0=s0-mean, d1=s1-mean;
  float ss=d0*d0+d1*d1;
  #pragma unroll
  for(int o=16;o;o>>=1) ss+=__shfl_xor_sync(0xffffffffu,ss,o);
  if(lane==0) sh[w]=ss;
  __syncthreads();
  float tot2=0.f;
  #pragma unroll
  for(int i=0;i<8;i++) tot2+=sh[i];
  float var=tot2*(1.0f/(float)(Dz-1));
  float r=1.0f/(sqrtf(var)+1e-6f);
  float v0=g[tid]*d0*r+be[tid];
  float v1=g[tid+256]*d1*r+be[tid+256];
  size_t o0=(size_t)n*Dz+tid, o1=o0+256;
  out[o0]=v0; out[o1]=v1;
  if (WH){
    oh[o0]=__float2half_rn(v0);
    oh[o1]=__float2half_rn(v1);
  }
}

extern "C" void kernel_launch(void* const* d_in, const int* in_sizes, int n_in,
                              void* d_out, int out_size)
{
  const float* x  =(const float*)d_in[0];
  const int* lens =(const int*)d_in[1];
  const float* Wq =(const float*)d_in[2];  const float* bq =(const float*)d_in[3];
  const float* Wk =(const float*)d_in[4];  const float* bk =(const float*)d_in[5];
  const float* Wv =(const float*)d_in[6];  const float* bv =(const float*)d_in[7];
  const float* Wo =(const float*)d_in[8];  const float* bo =(const float*)d_in[9];
  const float* W1 =(const float*)d_in[10]; const float* b1 =(const float*)d_in[11];
  const float* W2 =(const float*)d_in[12]; const float* b2 =(const float*)d_in[13];
  const float* g1 =(const float*)d_in[14]; const float* be1=(const float*)d_in[15];
  const float* g2 =(const float*)d_in[16]; const float* be2=(const float*)d_in[17];

  float* sc=nullptr;
  cudaGetSymbolAddress((void**)&sc, g_scratch);
  float *xb=sc+XBUF, *tb=sc+TBUF, *yb=sc+YBUF;
  hf *qh=(hf*)(sc+QHo), *kh=(hf*)(sc+KHo), *vth=(hf*)(sc+VTHo);
  hf *abh=(hf*)(sc+ABHo), *xh=(hf*)(sc+XHo), *yh=(hf*)(sc+YHo), *fh=(hf*)(sc+FHo);
  hf *wqh=(hf*)(sc+WQo), *wkh=(hf*)(sc+WKo), *wvh=(hf*)(sc+WVo), *woh=(hf*)(sc+WOo);
  hf *w1h=(hf*)(sc+W1o), *w2h=(hf*)(sc+W2o);

  cudaFuncSetAttribute(gemm_std_kernel<0>, cudaFuncAttributeMaxDynamicSharedMemorySize, GEMM_SMEM);
  cudaFuncSetAttribute(gemm_std_kernel<1>, cudaFuncAttributeMaxDynamicSharedMemorySize, GEMM_SMEM);
  cudaFuncSetAttribute(gemm_std_kernel<2>, cudaFuncAttributeMaxDynamicSharedMemorySize, GEMM_SMEM);
  cudaFuncSetAttribute(gemm_qkv_kernel, cudaFuncAttributeMaxDynamicSharedMemorySize, GEMM_SMEM);
  cudaFuncSetAttribute(flash_kernel, cudaFuncAttributeMaxDynamicSharedMemorySize, FLASH_SMEM);

  dim3 wb(32,8);
  wsplit_proj_kernel<<<dim3(16,16,16), wb>>>(Wq,Wk,Wv,Wo, wqh,wkh,wvh,woh);
  wsplit_ff_kernel<<<dim3(64,16,8), wb>>>(W1,W2, w1h,w2h);
  posenc_kernel<<<(Nz*Dz)/256, 256>>>(x, xb, xh);

  dim3 gqkv(12, Nz/256);           // (12,32)
  dim3 gproj(Dz/128, Nz/256);      // (4,32)
  dim3 gff1(FFz/128, Nz/256);      // (16,32)

  for (int l=0;l<Lz;l++){
    size_t wp=(size_t)l*Dz*Dz, wf=(size_t)l*Dz*FFz;
    gemm_qkv_kernel<<<gqkv,256,GEMM_SMEM>>>(xh,
      wqh+wp, wkh+wp, wvh+wp, bq+l*Dz, bk+l*Dz, bv+l*Dz,
      qh, kh, vth);

    flash_kernel<<<dim3(Sz/128, Bz*Hz),256,FLASH_SMEM>>>(qh,kh,vth,lens,abh);

    gemm_std_kernel<0><<<gproj,256,GEMM_SMEM>>>(abh, woh+wp, bo+l*Dz, tb, nullptr, Dz,Dz);
    ln_kernel<true><<<Nz,256>>>(xb,tb,g1+l*Dz,be1+l*Dz, yb,yh);

    gemm_std_kernel<1><<<gff1,256,GEMM_SMEM>>>(yh, w1h+wf, b1+(size_t)l*FFz, nullptr, fh, Dz,FFz);
    gemm_std_kernel<0><<<gproj,256,GEMM_SMEM>>>(fh, w2h+wf, b2+l*Dz, tb, nullptr, FFz,Dz);

    if (l==Lz-1)
      ln_kernel<false><<<Nz,256>>>(yb,tb,g2+l*Dz,be2+l*Dz,(float*)d_out,nullptr);
    else
      ln_kernel<true><<<Nz,256>>>(yb,tb,g2+l*Dz,be2+l*Dz, xb,xh);
  }
}

// round 15
// speedup vs baseline: 1.1532x; 1.1532x over previous
#include <cuda_runtime.h>
#include <cuda_fp16.h>
#include <cstdint>
#include <math.h>

#define Bz 8
#define Sz 1024
#define Dz 512
#define Hz 8
#define DHz 64
#define FFz 2048
#define Lz 4
#define Nz (Bz*Sz)

typedef __half hf;
typedef __half2 hf2;

static constexpr size_t NB = (size_t)Nz*Dz;
static constexpr size_t FBsz = (size_t)Nz*FFz;
static constexpr size_t WPROJ = (size_t)Lz*Dz*Dz;
static constexpr size_t WFF = (size_t)Lz*Dz*FFz;

static constexpr size_t XBUF=0, TBUF=NB, YBUF=2*NB,
  QHo=3*NB, KHo=QHo+NB/2, VTHo=KHo+NB/2, ABHo=VTHo+NB/2,
  XHo=ABHo+NB/2, YHo=XHo+NB/2, FHo=YHo+NB/2,
  WQo=FHo+FBsz/2, WKo=WQo+WPROJ/2, WVo=WKo+WPROJ/2, WOo=WVo+WPROJ/2,
  W1o=WOo+WPROJ/2, W2o=W1o+WFF/2, SCRATCH_TOTAL=W2o+WFF/2;

__device__ float g_scratch[SCRATCH_TOTAL];

__device__ __forceinline__ uint32_t smem_u32(const void* p){ return (uint32_t)__cvta_generic_to_shared(p); }
__device__ __forceinline__ uint32_t pack2h(float a, float b){
  hf2 t = __floats2half2_rn(a,b); uint32_t r; memcpy(&r,&t,4); return r; }

__device__ __forceinline__ void cp16(uint32_t d,const void* s){
  asm volatile("cp.async.cg.shared.global [%0],[%1],16;"::"r"(d),"l"(s):"memory"); }
#define CP_COMMIT() asm volatile("cp.async.commit_group;":::"memory")
#define CP_WAIT(n) asm volatile("cp.async.wait_group %0;"::"n"(n):"memory")

#define LDSM4(r,addr) asm volatile("ldmatrix.sync.aligned.m8n8.x4.shared.b16 {%0,%1,%2,%3},[%4];" \
  :"=r"((r)[0]),"=r"((r)[1]),"=r"((r)[2]),"=r"((r)[3]):"r"(addr))

#define MMA_F16(c,a,b) asm volatile( \
  "mma.sync.aligned.m16n8k16.row.col.f32.f16.f16.f32 {%0,%1,%2,%3},{%4,%5,%6,%7},{%8,%9},{%0,%1,%2,%3};" \
  : "+f"((c)[0]),"+f"((c)[1]),"+f"((c)[2]),"+f"((c)[3]) \
  : "r"((a)[0]),"r"((a)[1]),"r"((a)[2]),"r"((a)[3]),"r"((b)[0]),"r"((b)[1]))

// GEMM: CTA 128x128, warp 64x32, K-chunk 64 (128B rows), stage 32KB x3 = 96KB -> 2 CTA/SM
#define TILE_H 16384
#define STAGE_H 32768
static constexpr uint32_t GEMM_SMEM = 3*STAGE_H;

__device__ __forceinline__ uint32_t swz128(int r, int kby){
  return (uint32_t)(r*128 + ((kby) ^ ((r&7)*16)));
}

__device__ __forceinline__ void gemm_core(uint32_t sbase,
  const hf* bA, const hf* bB, int K, float (&acc)[4][4][4])
{
  int tid=threadIdx.x, wid=tid>>5, lane=tid&31;
  const hf* base[2] = { bA, bB };
  int KT = K>>6;

  auto load_chunk=[&](int kt,int s){
    uint32_t sb = sbase + (uint32_t)s*STAGE_H;
    int k0e = kt<<6;
    #pragma unroll
    for(int i=0;i<8;i++){
      int t = i>>2;
      int u = ((i&3)<<8) + tid;      // 0..1023
      int r = u>>3, c = u&7;
      cp16(sb + (uint32_t)(t*TILE_H) + swz128(r, c*16),
           base[t] + (size_t)r*K + k0e + c*8);
    }
  };

  int wm = wid&1, wn = wid>>1;
  int mA = wm*64 + (lane&7) + ((lane>>3)&1)*8;
  int kAby = ((lane>>4)&1)*16;
  int nB = wn*32 + (lane&7) + ((lane>>4)&1)*8;
  int kBby = ((lane>>3)&1)*16;

  load_chunk(0,0); CP_COMMIT();
  load_chunk(1,1); CP_COMMIT();

  for(int kt=0;kt<KT;kt++){
    if(kt+1<KT){ CP_WAIT(1); } else { CP_WAIT(0); }
    __syncthreads();
    if(kt+2<KT){ load_chunk(kt+2,(kt+2)%3); CP_COMMIT(); }
    uint32_t sb = sbase + (uint32_t)(kt%3)*STAGE_H;
    uint32_t sA=sb, sB=sb+TILE_H;
    #pragma unroll
    for(int st=0; st<4; st++){
      int kby0 = st*32;
      uint32_t af[16], bfr[8];
      #pragma unroll
      for(int mt=0;mt<4;mt++){
        int r = mA + mt*16;
        LDSM4(&af[mt*4], sA + swz128(r, kby0+kAby));
      }
      #pragma unroll
      for(int bt=0;bt<2;bt++){
        int n = nB + bt*16;
        LDSM4(&bfr[bt*4], sB + swz128(n, kby0+kBby));
      }
      #pragma unroll
      for(int mt=0;mt<4;mt++)
        #pragma unroll
        for(int nt=0;nt<4;nt++)
          MMA_F16(acc[mt][nt], &af[mt*4], &bfr[(nt>>1)*4 + (nt&1)*2]);
    }
  }
}

__device__ __forceinline__ void epi_f32(float (&acc)[4][4][4], const float* bias,
  float* C, int row0, int col0, int M, int wm, int wn, int lane)
{
  #pragma unroll
  for(int mt=0;mt<4;mt++){
    int r0 = row0 + wm*64 + mt*16 + (lane>>2);
    #pragma unroll
    for(int nt=0;nt<4;nt++){
      int c0i = col0 + wn*32 + nt*8 + 2*(lane&3);
      float b0v=bias[c0i], b1v=bias[c0i+1];
      float* a = acc[mt][nt];
      *(float2*)&C[(size_t)r0*M + c0i]     = make_float2(a[0]+b0v, a[1]+b1v);
      *(float2*)&C[(size_t)(r0+8)*M + c0i] = make_float2(a[2]+b0v, a[3]+b1v);
    }
  }
}

template<bool RELU>
__device__ __forceinline__ void epi_h(float (&acc)[4][4][4], const float* bias,
  hf* C, int row0, int col0, int M, int wm, int wn, int lane)
{
  #pragma unroll
  for(int mt=0;mt<4;mt++){
    int r0 = row0 + wm*64 + mt*16 + (lane>>2);
    #pragma unroll
    for(int nt=0;nt<4;nt++){
      int c0i = col0 + wn*32 + nt*8 + 2*(lane&3);
      float b0v=bias[c0i], b1v=bias[c0i+1];
      float* a = acc[mt][nt];
      float v00=a[0]+b0v, v01=a[1]+b1v, v10=a[2]+b0v, v11=a[3]+b1v;
      if(RELU){ v00=fmaxf(v00,0.f); v01=fmaxf(v01,0.f); v10=fmaxf(v10,0.f); v11=fmaxf(v11,0.f); }
      *(hf2*)&C[(size_t)r0*M + c0i]     = __floats2half2_rn(v00,v01);
      *(hf2*)&C[(size_t)(r0+8)*M + c0i] = __floats2half2_rn(v10,v11);
    }
  }
}

__device__ __forceinline__ void epi_vt(float (&acc)[4][4][4], const float* bias,
  hf* C, int row0, int col0, int wm, int wn, int lane)
{
  #pragma unroll
  for(int mt=0;mt<4;mt++){
    int r0 = row0 + wm*64 + mt*16 + (lane>>2);
    #pragma unroll
    for(int nt=0;nt<4;nt++){
      int c0i = col0 + wn*32 + nt*8 + 2*(lane&3);
      float b0v=bias[c0i], b1v=bias[c0i+1];
      float* a = acc[mt][nt];
      float v00=a[0]+b0v, v01=a[1]+b1v, v10=a[2]+b0v, v11=a[3]+b1v;
      int bI=r0>>10, sI=r0&1023, hI=c0i>>6, dI=c0i&63;
      size_t db = ((size_t)bI*Hz + hI)*DHz;
      C[(db+dI)*Sz+sI]   = __float2half_rn(v00);
      C[(db+dI+1)*Sz+sI] = __float2half_rn(v01);
      C[(db+dI)*Sz+sI+8]   = __float2half_rn(v10);
      C[(db+dI+1)*Sz+sI+8] = __float2half_rn(v11);
    }
  }
}

#define ACC_INIT(acc) { \
  _Pragma("unroll") \
  for(int mt=0;mt<4;mt++) \
    _Pragma("unroll") \
    for(int nt=0;nt<4;nt++){ acc[mt][nt][0]=0.f;acc[mt][nt][1]=0.f;acc[mt][nt][2]=0.f;acc[mt][nt][3]=0.f; } }

// MODE 0: fp32 out, 1: relu+half, 2: half
template<int MODE>
__global__ __launch_bounds__(256,2) void gemm_std_kernel(
  const hf* __restrict__ A, const hf* __restrict__ B,
  const float* __restrict__ bias, float* __restrict__ C,
  hf* __restrict__ Ch, int K, int M)
{
  extern __shared__ char smem[];
  uint32_t sbase = smem_u32(smem);
  int row0=blockIdx.y*128, col0=blockIdx.x*128;
  float acc[4][4][4];
  ACC_INIT(acc)
  gemm_core(sbase, A+(size_t)row0*K, B+(size_t)col0*K, K, acc);
  int wid=threadIdx.x>>5, lane=threadIdx.x&31;
  int wm=wid&1, wn=wid>>1;
  if(MODE==0) epi_f32(acc,bias,C,row0,col0,M,wm,wn,lane);
  else if(MODE==1) epi_h<true>(acc,bias,Ch,row0,col0,M,wm,wn,lane);
  else epi_h<false>(acc,bias,Ch,row0,col0,M,wm,wn,lane);
}

// merged QKV: blockIdx.x 0-3 Q, 4-7 K, 8-11 V(transpose)
__global__ __launch_bounds__(256,2) void gemm_qkv_kernel(
  const hf* __restrict__ A,
  const hf* __restrict__ Wq, const hf* __restrict__ Wk, const hf* __restrict__ Wv,
  const float* __restrict__ bq, const float* __restrict__ bk, const float* __restrict__ bv,
  hf* __restrict__ Qh, hf* __restrict__ Kh, hf* __restrict__ Vth)
{
  extern __shared__ char smem[];
  uint32_t sbase = smem_u32(smem);
  int sel = blockIdx.x>>2;
  int row0=blockIdx.y*128, col0=(blockIdx.x&3)*128;
  const hf* B = (sel==0)?Wq:(sel==1)?Wk:Wv;
  const float* bias = (sel==0)?bq:(sel==1)?bk:bv;
  float acc[4][4][4];
  ACC_INIT(acc)
  gemm_core(sbase, A+(size_t)row0*Dz, B+(size_t)col0*Dz, Dz, acc);
  int wid=threadIdx.x>>5, lane=threadIdx.x&31;
  int wm=wid&1, wn=wid>>1;
  if(sel==0) epi_h<false>(acc,bias,Qh,row0,col0,Dz,wm,wn,lane);
  else if(sel==1) epi_h<false>(acc,bias,Kh,row0,col0,Dz,wm,wn,lane);
  else epi_vt(acc,bias,Vth,row0,col0,wm,wn,lane);
}

// -------------------- fused flash attention (R13 config) --------------------
static constexpr uint32_t FLASH_SMEM = 16384 + 2*32768;

__global__ __launch_bounds__(256,2) void flash_kernel(
  const hf* __restrict__ Q, const hf* __restrict__ Km,
  const hf* __restrict__ Vt, const int* __restrict__ lens,
  hf* __restrict__ O)
{
  extern __shared__ char smem[];
  uint32_t sb = smem_u32(smem);
  uint32_t sQ=sb;
  int tid=threadIdx.x, wid=tid>>5, lane=tid&31;
  int bh=blockIdx.y, b=bh>>3, h=bh&7;
  int q0=blockIdx.x*128;
  int len = lens[b];
  int ntiles = (len+127)>>7;

  size_t qrow = ((size_t)b*Sz+q0)*Dz + h*DHz;
  for(int u=tid; u<1024; u+=256){
    int r=u>>3, c=u&7;
    uint32_t off=(uint32_t)(r*128 + ((c*16) ^ ((r&7)*16)));
    cp16(sQ+off, Q+qrow+(size_t)r*Dz+c*8);
  }
  auto load_kv=[&](int kt,int stg){
    uint32_t s0 = sb + 16384 + (uint32_t)stg*32768;
    int k0 = kt<<7;
    size_t krow = ((size_t)b*Sz+k0)*Dz + h*DHz;
    for(int u=tid; u<1024; u+=256){
      int r=u>>3, c=u&7;
      uint32_t off=(uint32_t)(r*128 + ((c*16) ^ ((r&7)*16)));
      cp16(s0+off, Km+krow+(size_t)r*Dz+c*8);
    }
    size_t vrow = (size_t)bh*DHz*Sz + k0;
    for(int u=tid; u<1024; u+=256){
      int r=u>>4, c=u&15;
      uint32_t off=(uint32_t)(r*256 + ((c*16) ^ ((r&7)*16)));
      cp16(s0+16384+off, Vt+vrow+(size_t)r*Sz+c*8);
    }
  };
  load_kv(0,0);
  CP_COMMIT();

  float mrow0=-1e30f, mrow1=-1e30f, lrow0=0.f, lrow1=0.f;
  float oacc[8][4];
  #pragma unroll
  for(int i=0;i<8;i++){
    #pragma unroll
    for(int j=0;j<4;j++) oacc[i][j]=0.f; }

  int rA = wid*16 + (lane&7) + ((lane>>3)&1)*8;
  int kAby = ((lane>>4)&1)*16;
  int nBb = (lane&7) + ((lane>>4)&1)*8;
  int kBby = ((lane>>3)&1)*16;
  uint32_t offaQ[4];
  #pragma unroll
  for(int st=0;st<4;st++)
    offaQ[st]=(uint32_t)(rA*128 + ((st*32+kAby) ^ ((rA&7)*16)));

  for(int kt=0;kt<ntiles;kt++){
    CP_WAIT(0);
    __syncthreads();
    if(kt+1<ntiles){ load_kv(kt+1,(kt+1)&1); CP_COMMIT(); }
    uint32_t s0 = sb + 16384 + (uint32_t)(kt&1)*32768;
    uint32_t sK=s0, sV=s0+16384;

    float sacc[16][4];
    #pragma unroll
    for(int i=0;i<16;i++){
      #pragma unroll
      for(int j=0;j<4;j++) sacc[i][j]=0.f; }

    #pragma unroll
    for(int st=0;st<4;st++){
      uint32_t af[4];
      LDSM4(af, sQ+offaQ[st]);
      #pragma unroll
      for(int g=0;g<8;g++){
        int n = g*16 + nBb;
        uint32_t offb=(uint32_t)(n*128 + ((st*32+kBby) ^ ((n&7)*16)));
        uint32_t bfr[4];
        LDSM4(bfr, sK+offb);
        MMA_F16(sacc[2*g],   af, &bfr[0]);
        MMA_F16(sacc[2*g+1], af, &bfr[2]);
      }
    }

    int k0 = kt<<7;
    bool need_mask = (k0+128 > len);
    #pragma unroll
    for(int nt=0;nt<16;nt++){
      #pragma unroll
      for(int j=0;j<4;j++){
        float s = sacc[nt][j]*0.125f;
        if(need_mask){
          int col = k0 + nt*8 + 2*(lane&3) + (j&1);
          if(col>=len) s=-1e30f;
        }
        sacc[nt][j]=s;
      }
    }
    float mx0=-1e30f, mx1=-1e30f;
    #pragma unroll
    for(int nt=0;nt<16;nt++){
      mx0=fmaxf(mx0,fmaxf(sacc[nt][0],sacc[nt][1]));
      mx1=fmaxf(mx1,fmaxf(sacc[nt][2],sacc[nt][3]));
    }
    mx0=fmaxf(mx0,__shfl_xor_sync(0xffffffffu,mx0,1));
    mx0=fmaxf(mx0,__shfl_xor_sync(0xffffffffu,mx0,2));
    mx1=fmaxf(mx1,__shfl_xor_sync(0xffffffffu,mx1,1));
    mx1=fmaxf(mx1,__shfl_xor_sync(0xffffffffu,mx1,2));
    float mn0=fmaxf(mrow0,mx0), mn1=fmaxf(mrow1,mx1);
    float sc0=__expf(mrow0-mn0), sc1=__expf(mrow1-mn1);
    mrow0=mn0; mrow1=mn1;
    float sum0=0.f, sum1=0.f;
    #pragma unroll
    for(int nt=0;nt<16;nt++){
      float p0=__expf(sacc[nt][0]-mn0), p1=__expf(sacc[nt][1]-mn0);
      float p2=__expf(sacc[nt][2]-mn1), p3=__expf(sacc[nt][3]-mn1);
      sacc[nt][0]=p0; sacc[nt][1]=p1; sacc[nt][2]=p2; sacc[nt][3]=p3;
      sum0+=p0+p1; sum1+=p2+p3;
    }
    sum0+=__shfl_xor_sync(0xffffffffu,sum0,1);
    sum0+=__shfl_xor_sync(0xffffffffu,sum0,2);
    sum1+=__shfl_xor_sync(0xffffffffu,sum1,1);
    sum1+=__shfl_xor_sync(0xffffffffu,sum1,2);
    lrow0=lrow0*sc0+sum0; lrow1=lrow1*sc1+sum1;
    #pragma unroll
    for(int nt=0;nt<8;nt++){
      oacc[nt][0]*=sc0; oacc[nt][1]*=sc0; oacc[nt][2]*=sc1; oacc[nt][3]*=sc1;
    }

    #pragma unroll
    for(int j=0;j<8;j++){
      uint32_t pa[4];
      pa[0]=pack2h(sacc[2*j][0],  sacc[2*j][1]);
      pa[1]=pack2h(sacc[2*j][2],  sacc[2*j][3]);
      pa[2]=pack2h(sacc[2*j+1][0],sacc[2*j+1][1]);
      pa[3]=pack2h(sacc[2*j+1][2],sacc[2*j+1][3]);
      #pragma unroll
      for(int g=0;g<4;g++){
        int n = g*16 + nBb;
        uint32_t offv=(uint32_t)(n*256 + ((j*32+kBby) ^ ((n&7)*16)));
        uint32_t vf[4];
        LDSM4(vf, sV+offv);
        MMA_F16(oacc[2*g],   pa, &vf[0]);
        MMA_F16(oacc[2*g+1], pa, &vf[2]);
      }
    }
  }

  float li0=1.f/lrow0, li1=1.f/lrow1;
  int r0 = q0 + wid*16 + (lane>>2);
  #pragma unroll
  for(int nt=0;nt<8;nt++){
    int c = h*64 + nt*8 + 2*(lane&3);
    size_t o0 = ((size_t)b*Sz+r0)*Dz + c;
    size_t o1 = o0 + (size_t)8*Dz;
    *(hf2*)&O[o0] = __floats2half2_rn(oacc[nt][0]*li0, oacc[nt][1]*li0);
    *(hf2*)&O[o1] = __floats2half2_rn(oacc[nt][2]*li1, oacc[nt][3]*li1);
  }
}

// -------------------- small kernels --------------------
__device__ __forceinline__ void wsplit_body(const float* Wz, hf* th,
  int K, int M, int m0, int k0, size_t zo)
{
  __shared__ float t[32][33];
  int tx=threadIdx.x, ty=threadIdx.y;
  #pragma unroll
  for(int j=0;j<4;j++) t[ty+8*j][tx] = Wz[(size_t)(k0+ty+8*j)*M + m0+tx];
  __syncthreads();
  #pragma unroll
  for(int j=0;j<4;j++){
    size_t o = zo + (size_t)(m0+ty+8*j)*K + k0+tx;
    th[o] = __float2half_rn(t[tx][ty+8*j]);
  }
}

__global__ __launch_bounds__(256) void wsplit_proj_kernel(
  const float* __restrict__ Wq, const float* __restrict__ Wk,
  const float* __restrict__ Wv, const float* __restrict__ Wo,
  hf* qh, hf* kh, hf* vh, hf* oh)
{
  int w = blockIdx.z & 3, l = blockIdx.z >> 2;
  const float* W; hf* th;
  switch(w){
    case 0: W=Wq; th=qh; break;
    case 1: W=Wk; th=kh; break;
    case 2: W=Wv; th=vh; break;
    default: W=Wo; th=oh; break;
  }
  size_t zo = (size_t)l*Dz*Dz;
  wsplit_body(W+zo, th, Dz, Dz, blockIdx.x*32, blockIdx.y*32, zo);
}

__global__ __launch_bounds__(256) void wsplit_ff_kernel(
  const float* __restrict__ W1, const float* __restrict__ W2,
  hf* h1, hf* h2)
{
  int which = blockIdx.z>>2, l = blockIdx.z&3;
  size_t zo = (size_t)l*Dz*FFz;
  if(which==0)
    wsplit_body(W1+zo, h1, Dz, FFz, blockIdx.x*32, blockIdx.y*32, zo);
  else
    wsplit_body(W2+zo, h2, FFz, Dz, blockIdx.y*32, blockIdx.x*32, zo);
}

__global__ __launch_bounds__(256) void posenc_kernel(const float* __restrict__ x,
  float* __restrict__ out, hf* __restrict__ oh)
{
  int idx = blockIdx.x*256 + threadIdx.x;
  int d = idx & (Dz-1), s = (idx>>9) & (Sz-1);
  int i2 = d & ~1;
  float divv = (float)exp((double)i2 * (-9.210340371976184/(double)Dz));
  float ang = (float)s * divv;
  float pe = (d&1) ? cosf(ang) : sinf(ang);
  float v = x[idx] + pe;
  out[idx] = v;
  oh[idx] = __float2half_rn(v);
}

template<bool WH>
__global__ __launch_bounds__(256) void ln_kernel(
  const float* __restrict__ Xa, const float* __restrict__ Xb,
  const float* __restrict__ g, const float* __restrict__ be,
  float* __restrict__ out, hf* __restrict__ oh)
{
  int n=blockIdx.x;
  const float* a = Xa + (size_t)n*Dz;
  const float* c = Xb + (size_t)n*Dz;
  int tid=threadIdx.x, lane=tid&31, w=tid>>5;
  __shared__ float sh[8];
  float s0=a[tid]+c[tid], s1=a[tid+256]+c[tid+256];
  float sum=s0+s1;
  #pragma unroll
  for(int o=16;o;o>>=1) sum+=__shfl_xor_sync(0xffffffffu,sum,o);
  if(lane==0) sh[w]=sum;
  __syncthreads();
  float tot=0.f;
  #pragma unroll
  for(int i=0;i<8;i++) tot+=sh[i];
  __syncthreads();
  float mean=tot*(1.0f/(float)Dz);
  float d0=s0-mean, d1=s1-mean;
  float ss=d0*d0+d1*d1;
  #pragma unroll
  for(int o=16;o;o>>=1) ss+=__shfl_xor_sync(0xffffffffu,ss,o);
  if(lane==0) sh[w]=ss;
  __syncthreads();
  float tot2=0.f;
  #pragma unroll
  for(int i=0;i<8;i++) tot2+=sh[i];
  float var=tot2*(1.0f/(float)(Dz-1));
  float r=1.0f/(sqrtf(var)+1e-6f);
  float v0=g[tid]*d0*r+be[tid];
  float v1=g[tid+256]*d1*r+be[tid+256];
  size_t o0=(size_t)n*Dz+tid, o1=o0+256;
  out[o0]=v0; out[o1]=v1;
  if (WH){
    oh[o0]=__float2half_rn(v0);
    oh[o1]=__float2half_rn(v1);
  }
}

extern "C" void kernel_launch(void* const* d_in, const int* in_sizes, int n_in,
                              void* d_out, int out_size)
{
  const float* x  =(const float*)d_in[0];
  const int* lens =(const int*)d_in[1];
  const float* Wq =(const float*)d_in[2];  const float* bq =(const float*)d_in[3];
  const float* Wk =(const float*)d_in[4];  const float* bk =(const float*)d_in[5];
  const float* Wv =(const float*)d_in[6];  const float* bv =(const float*)d_in[7];
  const float* Wo =(const float*)d_in[8];  const float* bo =(const float*)d_in[9];
  const float* W1 =(const float*)d_in[10]; const float* b1 =(const float*)d_in[11];
  const float* W2 =(const float*)d_in[12]; const float* b2 =(const float*)d_in[13];
  const float* g1 =(const float*)d_in[14]; const float* be1=(const float*)d_in[15];
  const float* g2 =(const float*)d_in[16]; const float* be2=(const float*)d_in[17];

  float* sc=nullptr;
  cudaGetSymbolAddress((void**)&sc, g_scratch);
  float *xb=sc+XBUF, *tb=sc+TBUF, *yb=sc+YBUF;
  hf *qh=(hf*)(sc+QHo), *kh=(hf*)(sc+KHo), *vth=(hf*)(sc+VTHo);
  hf *abh=(hf*)(sc+ABHo), *xh=(hf*)(sc+XHo), *yh=(hf*)(sc+YHo), *fh=(hf*)(sc+FHo);
  hf *wqh=(hf*)(sc+WQo), *wkh=(hf*)(sc+WKo), *wvh=(hf*)(sc+WVo), *woh=(hf*)(sc+WOo);
  hf *w1h=(hf*)(sc+W1o), *w2h=(hf*)(sc+W2o);

  cudaFuncSetAttribute(gemm_std_kernel<0>, cudaFuncAttributeMaxDynamicSharedMemorySize, GEMM_SMEM);
  cudaFuncSetAttribute(gemm_std_kernel<1>, cudaFuncAttributeMaxDynamicSharedMemorySize, GEMM_SMEM);
  cudaFuncSetAttribute(gemm_std_kernel<2>, cudaFuncAttributeMaxDynamicSharedMemorySize, GEMM_SMEM);
  cudaFuncSetAttribute(gemm_qkv_kernel, cudaFuncAttributeMaxDynamicSharedMemorySize, GEMM_SMEM);
  cudaFuncSetAttribute(flash_kernel, cudaFuncAttributeMaxDynamicSharedMemorySize, FLASH_SMEM);

  dim3 wb(32,8);
  wsplit_proj_kernel<<<dim3(16,16,16), wb>>>(Wq,Wk,Wv,Wo, wqh,wkh,wvh,woh);
  wsplit_ff_kernel<<<dim3(64,16,8), wb>>>(W1,W2, w1h,w2h);
  posenc_kernel<<<(Nz*Dz)/256, 256>>>(x, xb, xh);

  dim3 gqkv(12, Nz/128);
  dim3 gproj(Dz/128, Nz/128);
  dim3 gff1(FFz/128, Nz/128);

  for (int l=0;l<Lz;l++){
    size_t wp=(size_t)l*Dz*Dz, wf=(size_t)l*Dz*FFz;
    gemm_qkv_kernel<<<gqkv,256,GEMM_SMEM>>>(xh,
      wqh+wp, wkh+wp, wvh+wp, bq+l*Dz, bk+l*Dz, bv+l*Dz,
      qh, kh, vth);

    flash_kernel<<<dim3(Sz/128, Bz*Hz),256,FLASH_SMEM>>>(qh,kh,vth,lens,abh);

    gemm_std_kernel<0><<<gproj,256,GEMM_SMEM>>>(abh, woh+wp, bo+l*Dz, tb, nullptr, Dz,Dz);
    ln_kernel<true><<<Nz,256>>>(xb,tb,g1+l*Dz,be1+l*Dz, yb,yh);

    gemm_std_kernel<1><<<gff1,256,GEMM_SMEM>>>(yh, w1h+wf, b1+(size_t)l*FFz, nullptr, fh, Dz,FFz);
    gemm_std_kernel<0><<<gproj,256,GEMM_SMEM>>>(fh, w2h+wf, b2+l*Dz, tb, nullptr, FFz,Dz);

    if (l==Lz-1)
      ln_kernel<false><<<Nz,256>>>(yb,tb,g2+l*Dz,be2+l*Dz,(float*)d_out,nullptr);
    else
      ln_kernel<true><<<Nz,256>>>(yb,tb,g2+l*Dz,be2+l*Dz, xb,xh);
  }
}

// round 16
// speedup vs baseline: 1.1550x; 1.0015x over previous
#include <cuda_runtime.h>
#include <cuda_fp16.h>
#include <cstdint>
#include <math.h>

#define Bz 8
#define Sz 1024
#define Dz 512
#define Hz 8
#define DHz 64
#define FFz 2048
#define Lz 4
#define Nz (Bz*Sz)

typedef __half hf;
typedef __half2 hf2;

static constexpr size_t NB = (size_t)Nz*Dz;
static constexpr size_t FBsz = (size_t)Nz*FFz;
static constexpr size_t WPROJ = (size_t)Lz*Dz*Dz;
static constexpr size_t WFF = (size_t)Lz*Dz*FFz;

static constexpr size_t XBUF=0, TBUF=NB, YBUF=2*NB,
  QHo=3*NB, KHo=QHo+NB/2, VTHo=KHo+NB/2, ABHo=VTHo+NB/2,
  XHo=ABHo+NB/2, YHo=XHo+NB/2, FHo=YHo+NB/2,
  WQo=FHo+FBsz/2, WKo=WQo+WPROJ/2, WVo=WKo+WPROJ/2, WOo=WVo+WPROJ/2,
  W1o=WOo+WPROJ/2, W2o=W1o+WFF/2, SCRATCH_TOTAL=W2o+WFF/2;

__device__ float g_scratch[SCRATCH_TOTAL];

__device__ __forceinline__ uint32_t smem_u32(const void* p){ return (uint32_t)__cvta_generic_to_shared(p); }
__device__ __forceinline__ uint32_t pack2h(float a, float b){
  hf2 t = __floats2half2_rn(a,b); uint32_t r; memcpy(&r,&t,4); return r; }

__device__ __forceinline__ void cp16(uint32_t d,const void* s){
  asm volatile("cp.async.cg.shared.global [%0],[%1],16;"::"r"(d),"l"(s):"memory"); }
#define CP_COMMIT() asm volatile("cp.async.commit_group;":::"memory")
#define CP_WAIT(n) asm volatile("cp.async.wait_group %0;"::"n"(n):"memory")

#define LDSM4(r,addr) asm volatile("ldmatrix.sync.aligned.m8n8.x4.shared.b16 {%0,%1,%2,%3},[%4];" \
  :"=r"((r)[0]),"=r"((r)[1]),"=r"((r)[2]),"=r"((r)[3]):"r"(addr))

#define MMA_F16(c,a,b) asm volatile( \
  "mma.sync.aligned.m16n8k16.row.col.f32.f16.f16.f32 {%0,%1,%2,%3},{%4,%5,%6,%7},{%8,%9},{%0,%1,%2,%3};" \
  : "+f"((c)[0]),"+f"((c)[1]),"+f"((c)[2]),"+f"((c)[3]) \
  : "r"((a)[0]),"r"((a)[1]),"r"((a)[2]),"r"((a)[3]),"r"((b)[0]),"r"((b)[1]))

// GEMM: CTA 128x128, 128 threads = 4 warps of 64x64 (2x2). K-chunk 64, stage 32KB x3 -> 2 CTA/SM
#define TILE_H 16384
#define STAGE_H 32768
static constexpr uint32_t GEMM_SMEM = 3*STAGE_H;

__device__ __forceinline__ uint32_t swz128(int r, int kby){
  return (uint32_t)(r*128 + ((kby) ^ ((r&7)*16)));
}

__device__ __forceinline__ void gemm_core(uint32_t sbase,
  const hf* bA, const hf* bB, int K, float (&acc)[4][8][4])
{
  int tid=threadIdx.x, wid=tid>>5, lane=tid&31;
  const hf* base[2] = { bA, bB };
  int KT = K>>6;

  auto load_chunk=[&](int kt,int s){
    uint32_t sb = sbase + (uint32_t)s*STAGE_H;
    int k0e = kt<<6;
    #pragma unroll
    for(int i=0;i<16;i++){
      int t = i>>3;
      int u = ((i&7)<<7) + tid;      // 0..1023
      int r = u>>3, c = u&7;
      cp16(sb + (uint32_t)(t*TILE_H) + swz128(r, c*16),
           base[t] + (size_t)r*K + k0e + c*8);
    }
  };

  int wm = wid>>1, wn = wid&1;
  int mA = wm*64 + (lane&7) + ((lane>>3)&1)*8;
  int kAby = ((lane>>4)&1)*16;
  int nB0 = wn*64 + (lane&7) + ((lane>>4)&1)*8;
  int kBby = ((lane>>3)&1)*16;

  load_chunk(0,0); CP_COMMIT();
  load_chunk(1,1); CP_COMMIT();

  for(int kt=0;kt<KT;kt++){
    if(kt+1<KT){ CP_WAIT(1); } else { CP_WAIT(0); }
    __syncthreads();
    if(kt+2<KT){ load_chunk(kt+2,(kt+2)%3); CP_COMMIT(); }
    uint32_t sb = sbase + (uint32_t)(kt%3)*STAGE_H;
    uint32_t sA=sb, sB=sb+TILE_H;
    #pragma unroll
    for(int st=0; st<4; st++){
      int kby0 = st*32;
      uint32_t af[16];
      #pragma unroll
      for(int mt=0;mt<4;mt++){
        int r = mA + mt*16;
        LDSM4(&af[mt*4], sA + swz128(r, kby0+kAby));
      }
      #pragma unroll
      for(int hv=0; hv<2; hv++){
        uint32_t bfr[8];
        #pragma unroll
        for(int bt=0;bt<2;bt++){
          int n = nB0 + (hv*2+bt)*16;
          LDSM4(&bfr[bt*4], sB + swz128(n, kby0+kBby));
        }
        #pragma unroll
        for(int mt=0;mt<4;mt++)
          #pragma unroll
          for(int nt=0;nt<4;nt++)
            MMA_F16(acc[mt][hv*4+nt], &af[mt*4], &bfr[(nt>>1)*4 + (nt&1)*2]);
      }
    }
  }
}

__device__ __forceinline__ void epi_f32(float (&acc)[4][8][4], const float* bias,
  float* C, int row0, int col0, int M, int wm, int wn, int lane)
{
  #pragma unroll
  for(int mt=0;mt<4;mt++){
    int r0 = row0 + wm*64 + mt*16 + (lane>>2);
    #pragma unroll
    for(int nt=0;nt<8;nt++){
      int c0i = col0 + wn*64 + nt*8 + 2*(lane&3);
      float b0v=bias[c0i], b1v=bias[c0i+1];
      float* a = acc[mt][nt];
      *(float2*)&C[(size_t)r0*M + c0i]     = make_float2(a[0]+b0v, a[1]+b1v);
      *(float2*)&C[(size_t)(r0+8)*M + c0i] = make_float2(a[2]+b0v, a[3]+b1v);
    }
  }
}

template<bool RELU>
__device__ __forceinline__ void epi_h(float (&acc)[4][8][4], const float* bias,
  hf* C, int row0, int col0, int M, int wm, int wn, int lane)
{
  #pragma unroll
  for(int mt=0;mt<4;mt++){
    int r0 = row0 + wm*64 + mt*16 + (lane>>2);
    #pragma unroll
    for(int nt=0;nt<8;nt++){
      int c0i = col0 + wn*64 + nt*8 + 2*(lane&3);
      float b0v=bias[c0i], b1v=bias[c0i+1];
      float* a = acc[mt][nt];
      float v00=a[0]+b0v, v01=a[1]+b1v, v10=a[2]+b0v, v11=a[3]+b1v;
      if(RELU){ v00=fmaxf(v00,0.f); v01=fmaxf(v01,0.f); v10=fmaxf(v10,0.f); v11=fmaxf(v11,0.f); }
      *(hf2*)&C[(size_t)r0*M + c0i]     = __floats2half2_rn(v00,v01);
      *(hf2*)&C[(size_t)(r0+8)*M + c0i] = __floats2half2_rn(v10,v11);
    }
  }
}

__device__ __forceinline__ void epi_vt(float (&acc)[4][8][4], const float* bias,
  hf* C, int row0, int col0, int wm, int wn, int lane)
{
  #pragma unroll
  for(int mt=0;mt<4;mt++){
    int r0 = row0 + wm*64 + mt*16 + (lane>>2);
    #pragma unroll
    for(int nt=0;nt<8;nt++){
      int c0i = col0 + wn*64 + nt*8 + 2*(lane&3);
      float b0v=bias[c0i], b1v=bias[c0i+1];
      float* a = acc[mt][nt];
      float v00=a[0]+b0v, v01=a[1]+b1v, v10=a[2]+b0v, v11=a[3]+b1v;
      int bI=r0>>10, sI=r0&1023, hI=c0i>>6, dI=c0i&63;
      size_t db = ((size_t)bI*Hz + hI)*DHz;
      C[(db+dI)*Sz+sI]   = __float2half_rn(v00);
      C[(db+dI+1)*Sz+sI] = __float2half_rn(v01);
      C[(db+dI)*Sz+sI+8]   = __float2half_rn(v10);
      C[(db+dI+1)*Sz+sI+8] = __float2half_rn(v11);
    }
  }
}

#define ACC_INIT(acc) { \
  _Pragma("unroll") \
  for(int mt=0;mt<4;mt++) \
    _Pragma("unroll") \
    for(int nt=0;nt<8;nt++){ acc[mt][nt][0]=0.f;acc[mt][nt][1]=0.f;acc[mt][nt][2]=0.f;acc[mt][nt][3]=0.f; } }

// MODE 0: fp32 out, 1: relu+half, 2: half
template<int MODE>
__global__ __launch_bounds__(128,2) void gemm_std_kernel(
  const hf* __restrict__ A, const hf* __restrict__ B,
  const float* __restrict__ bias, float* __restrict__ C,
  hf* __restrict__ Ch, int K, int M)
{
  extern __shared__ char smem[];
  uint32_t sbase = smem_u32(smem);
  int row0=blockIdx.y*128, col0=blockIdx.x*128;
  float acc[4][8][4];
  ACC_INIT(acc)
  gemm_core(sbase, A+(size_t)row0*K, B+(size_t)col0*K, K, acc);
  int wid=threadIdx.x>>5, lane=threadIdx.x&31;
  int wm=wid>>1, wn=wid&1;
  if(MODE==0) epi_f32(acc,bias,C,row0,col0,M,wm,wn,lane);
  else if(MODE==1) epi_h<true>(acc,bias,Ch,row0,col0,M,wm,wn,lane);
  else epi_h<false>(acc,bias,Ch,row0,col0,M,wm,wn,lane);
}

// merged QKV: blockIdx.x 0-3 Q, 4-7 K, 8-11 V(transpose)
__global__ __launch_bounds__(128,2) void gemm_qkv_kernel(
  const hf* __restrict__ A,
  const hf* __restrict__ Wq, const hf* __restrict__ Wk, const hf* __restrict__ Wv,
  const float* __restrict__ bq, const float* __restrict__ bk, const float* __restrict__ bv,
  hf* __restrict__ Qh, hf* __restrict__ Kh, hf* __restrict__ Vth)
{
  extern __shared__ char smem[];
  uint32_t sbase = smem_u32(smem);
  int sel = blockIdx.x>>2;
  int row0=blockIdx.y*128, col0=(blockIdx.x&3)*128;
  const hf* B = (sel==0)?Wq:(sel==1)?Wk:Wv;
  const float* bias = (sel==0)?bq:(sel==1)?bk:bv;
  float acc[4][8][4];
  ACC_INIT(acc)
  gemm_core(sbase, A+(size_t)row0*Dz, B+(size_t)col0*Dz, Dz, acc);
  int wid=threadIdx.x>>5, lane=threadIdx.x&31;
  int wm=wid>>1, wn=wid&1;
  if(sel==0) epi_h<false>(acc,bias,Qh,row0,col0,Dz,wm,wn,lane);
  else if(sel==1) epi_h<false>(acc,bias,Kh,row0,col0,Dz,wm,wn,lane);
  else epi_vt(acc,bias,Vth,row0,col0,wm,wn,lane);
}

// -------------------- fused flash attention (R13 config, unchanged) --------------------
static constexpr uint32_t FLASH_SMEM = 16384 + 2*32768;

__global__ __launch_bounds__(256,2) void flash_kernel(
  const hf* __restrict__ Q, const hf* __restrict__ Km,
  const hf* __restrict__ Vt, const int* __restrict__ lens,
  hf* __restrict__ O)
{
  extern __shared__ char smem[];
  uint32_t sb = smem_u32(smem);
  uint32_t sQ=sb;
  int tid=threadIdx.x, wid=tid>>5, lane=tid&31;
  int bh=blockIdx.y, b=bh>>3, h=bh&7;
  int q0=blockIdx.x*128;
  int len = lens[b];
  int ntiles = (len+127)>>7;

  size_t qrow = ((size_t)b*Sz+q0)*Dz + h*DHz;
  for(int u=tid; u<1024; u+=256){
    int r=u>>3, c=u&7;
    uint32_t off=(uint32_t)(r*128 + ((c*16) ^ ((r&7)*16)));
    cp16(sQ+off, Q+qrow+(size_t)r*Dz+c*8);
  }
  auto load_kv=[&](int kt,int stg){
    uint32_t s0 = sb + 16384 + (uint32_t)stg*32768;
    int k0 = kt<<7;
    size_t krow = ((size_t)b*Sz+k0)*Dz + h*DHz;
    for(int u=tid; u<1024; u+=256){
      int r=u>>3, c=u&7;
      uint32_t off=(uint32_t)(r*128 + ((c*16) ^ ((r&7)*16)));
      cp16(s0+off, Km+krow+(size_t)r*Dz+c*8);
    }
    size_t vrow = (size_t)bh*DHz*Sz + k0;
    for(int u=tid; u<1024; u+=256){
      int r=u>>4, c=u&15;
      uint32_t off=(uint32_t)(r*256 + ((c*16) ^ ((r&7)*16)));
      cp16(s0+16384+off, Vt+vrow+(size_t)r*Sz+c*8);
    }
  };
  load_kv(0,0);
  CP_COMMIT();

  float mrow0=-1e30f, mrow1=-1e30f, lrow0=0.f, lrow1=0.f;
  float oacc[8][4];
  #pragma unroll
  for(int i=0;i<8;i++){
    #pragma unroll
    for(int j=0;j<4;j++) oacc[i][j]=0.f; }

  int rA = wid*16 + (lane&7) + ((lane>>3)&1)*8;
  int kAby = ((lane>>4)&1)*16;
  int nBb = (lane&7) + ((lane>>4)&1)*8;
  int kBby = ((lane>>3)&1)*16;
  uint32_t offaQ[4];
  #pragma unroll
  for(int st=0;st<4;st++)
    offaQ[st]=(uint32_t)(rA*128 + ((st*32+kAby) ^ ((rA&7)*16)));

  for(int kt=0;kt<ntiles;kt++){
    CP_WAIT(0);
    __syncthreads();
    if(kt+1<ntiles){ load_kv(kt+1,(kt+1)&1); CP_COMMIT(); }
    uint32_t s0 = sb + 16384 + (uint32_t)(kt&1)*32768;
    uint32_t sK=s0, sV=s0+16384;

    float sacc[16][4];
    #pragma unroll
    for(int i=0;i<16;i++){
      #pragma unroll
      for(int j=0;j<4;j++) sacc[i][j]=0.f; }

    #pragma unroll
    for(int st=0;st<4;st++){
      uint32_t af[4];
      LDSM4(af, sQ+offaQ[st]);
      #pragma unroll
      for(int g=0;g<8;g++){
        int n = g*16 + nBb;
        uint32_t offb=(uint32_t)(n*128 + ((st*32+kBby) ^ ((n&7)*16)));
        uint32_t bfr[4];
        LDSM4(bfr, sK+offb);
        MMA_F16(sacc[2*g],   af, &bfr[0]);
        MMA_F16(sacc[2*g+1], af, &bfr[2]);
      }
    }

    int k0 = kt<<7;
    bool need_mask = (k0+128 > len);
    #pragma unroll
    for(int nt=0;nt<16;nt++){
      #pragma unroll
      for(int j=0;j<4;j++){
        float s = sacc[nt][j]*0.125f;
        if(need_mask){
          int col = k0 + nt*8 + 2*(lane&3) + (j&1);
          if(col>=len) s=-1e30f;
        }
        sacc[nt][j]=s;
      }
    }
    float mx0=-1e30f, mx1=-1e30f;
    #pragma unroll
    for(int nt=0;nt<16;nt++){
      mx0=fmaxf(mx0,fmaxf(sacc[nt][0],sacc[nt][1]));
      mx1=fmaxf(mx1,fmaxf(sacc[nt][2],sacc[nt][3]));
    }
    mx0=fmaxf(mx0,__shfl_xor_sync(0xffffffffu,mx0,1));
    mx0=fmaxf(mx0,__shfl_xor_sync(0xffffffffu,mx0,2));
    mx1=fmaxf(mx1,__shfl_xor_sync(0xffffffffu,mx1,1));
    mx1=fmaxf(mx1,__shfl_xor_sync(0xffffffffu,mx1,2));
    float mn0=fmaxf(mrow0,mx0), mn1=fmaxf(mrow1,mx1);
    float sc0=__expf(mrow0-mn0), sc1=__expf(mrow1-mn1);
    mrow0=mn0; mrow1=mn1;
    float sum0=0.f, sum1=0.f;
    #pragma unroll
    for(int nt=0;nt<16;nt++){
      float p0=__expf(sacc[nt][0]-mn0), p1=__expf(sacc[nt][1]-mn0);
      float p2=__expf(sacc[nt][2]-mn1), p3=__expf(sacc[nt][3]-mn1);
      sacc[nt][0]=p0; sacc[nt][1]=p1; sacc[nt][2]=p2; sacc[nt][3]=p3;
      sum0+=p0+p1; sum1+=p2+p3;
    }
    sum0+=__shfl_xor_sync(0xffffffffu,sum0,1);
    sum0+=__shfl_xor_sync(0xffffffffu,sum0,2);
    sum1+=__shfl_xor_sync(0xffffffffu,sum1,1);
    sum1+=__shfl_xor_sync(0xffffffffu,sum1,2);
    lrow0=lrow0*sc0+sum0; lrow1=lrow1*sc1+sum1;
    #pragma unroll
    for(int nt=0;nt<8;nt++){
      oacc[nt][0]*=sc0; oacc[nt][1]*=sc0; oacc[nt][2]*=sc1; oacc[nt][3]*=sc1;
    }

    #pragma unroll
    for(int j=0;j<8;j++){
      uint32_t pa[4];
      pa[0]=pack2h(sacc[2*j][0],  sacc[2*j][1]);
      pa[1]=pack2h(sacc[2*j][2],  sacc[2*j][3]);
      pa[2]=pack2h(sacc[2*j+1][0],sacc[2*j+1][1]);
      pa[3]=pack2h(sacc[2*j+1][2],sacc[2*j+1][3]);
      #pragma unroll
      for(int g=0;g<4;g++){
        int n = g*16 + nBb;
        uint32_t offv=(uint32_t)(n*256 + ((j*32+kBby) ^ ((n&7)*16)));
        uint32_t vf[4];
        LDSM4(vf, sV+offv);
        MMA_F16(oacc[2*g],   pa, &vf[0]);
        MMA_F16(oacc[2*g+1], pa, &vf[2]);
      }
    }
  }

  float li0=1.f/lrow0, li1=1.f/lrow1;
  int r0 = q0 + wid*16 + (lane>>2);
  #pragma unroll
  for(int nt=0;nt<8;nt++){
    int c = h*64 + nt*8 + 2*(lane&3);
    size_t o0 = ((size_t)b*Sz+r0)*Dz + c;
    size_t o1 = o0 + (size_t)8*Dz;
    *(hf2*)&O[o0] = __floats2half2_rn(oacc[nt][0]*li0, oacc[nt][1]*li0);
    *(hf2*)&O[o1] = __floats2half2_rn(oacc[nt][2]*li1, oacc[nt][3]*li1);
  }
}

// -------------------- small kernels --------------------
__device__ __forceinline__ void wsplit_body(const float* Wz, hf* th,
  int K, int M, int m0, int k0, size_t zo)
{
  __shared__ float t[32][33];
  int tx=threadIdx.x, ty=threadIdx.y;
  #pragma unroll
  for(int j=0;j<4;j++) t[ty+8*j][tx] = Wz[(size_t)(k0+ty+8*j)*M + m0+tx];
  __syncthreads();
  #pragma unroll
  for(int j=0;j<4;j++){
    size_t o = zo + (size_t)(m0+ty+8*j)*K + k0+tx;
    th[o] = __float2half_rn(t[tx][ty+8*j]);
  }
}

__global__ __launch_bounds__(256) void wsplit_proj_kernel(
  const float* __restrict__ Wq, const float* __restrict__ Wk,
  const float* __restrict__ Wv, const float* __restrict__ Wo,
  hf* qh, hf* kh, hf* vh, hf* oh)
{
  int w = blockIdx.z & 3, l = blockIdx.z >> 2;
  const float* W; hf* th;
  switch(w){
    case 0: W=Wq; th=qh; break;
    case 1: W=Wk; th=kh; break;
    case 2: W=Wv; th=vh; break;
    default: W=Wo; th=oh; break;
  }
  size_t zo = (size_t)l*Dz*Dz;
  wsplit_body(W+zo, th, Dz, Dz, blockIdx.x*32, blockIdx.y*32, zo);
}

__global__ __launch_bounds__(256) void wsplit_ff_kernel(
  const float* __restrict__ W1, const float* __restrict__ W2,
  hf* h1, hf* h2)
{
  int which = blockIdx.z>>2, l = blockIdx.z&3;
  size_t zo = (size_t)l*Dz*FFz;
  if(which==0)
    wsplit_body(W1+zo, h1, Dz, FFz, blockIdx.x*32, blockIdx.y*32, zo);
  else
    wsplit_body(W2+zo, h2, FFz, Dz, blockIdx.y*32, blockIdx.x*32, zo);
}

__global__ __launch_bounds__(256) void posenc_kernel(const float* __restrict__ x,
  float* __restrict__ out, hf* __restrict__ oh)
{
  int idx = blockIdx.x*256 + threadIdx.x;
  int d = idx & (Dz-1), s = (idx>>9) & (Sz-1);
  int i2 = d & ~1;
  float divv = (float)exp((double)i2 * (-9.210340371976184/(double)Dz));
  float ang = (float)s * divv;
  float pe = (d&1) ? cosf(ang) : sinf(ang);
  float v = x[idx] + pe;
  out[idx] = v;
  oh[idx] = __float2half_rn(v);
}

template<bool WH>
__global__ __launch_bounds__(256) void ln_kernel(
  const float* __restrict__ Xa, const float* __restrict__ Xb,
  const float* __restrict__ g, const float* __restrict__ be,
  float* __restrict__ out, hf* __restrict__ oh)
{
  int n=blockIdx.x;
  const float* a = Xa + (size_t)n*Dz;
  const float* c = Xb + (size_t)n*Dz;
  int tid=threadIdx.x, lane=tid&31, w=tid>>5;
  __shared__ float sh[8];
  float s0=a[tid]+c[tid], s1=a[tid+256]+c[tid+256];
  float sum=s0+s1;
  #pragma unroll
  for(int o=16;o;o>>=1) sum+=__shfl_xor_sync(0xffffffffu,sum,o);
  if(lane==0) sh[w]=sum;
  __syncthreads();
  float tot=0.f;
  #pragma unroll
  for(int i=0;i<8;i++) tot+=sh[i];
  __syncthreads();
  float mean=tot*(1.0f/(float)Dz);
  float d0=s0-mean, d1=s1-mean;
  float ss=d0*d0+d1*d1;
  #pragma unroll
  for(int o=16;o;o>>=1) ss+=__shfl_xor_sync(0xffffffffu,ss,o);
  if(lane==0) sh[w]=ss;
  __syncthreads();
  float tot2=0.f;
  #pragma unroll
  for(int i=0;i<8;i++) tot2+=sh[i];
  float var=tot2*(1.0f/(float)(Dz-1));
  float r=1.0f/(sqrtf(var)+1e-6f);
  float v0=g[tid]*d0*r+be[tid];
  float v1=g[tid+256]*d1*r+be[tid+256];
  size_t o0=(size_t)n*Dz+tid, o1=o0+256;
  out[o0]=v0; out[o1]=v1;
  if (WH){
    oh[o0]=__float2half_rn(v0);
    oh[o1]=__float2half_rn(v1);
  }
}

extern "C" void kernel_launch(void* const* d_in, const int* in_sizes, int n_in,
                              void* d_out, int out_size)
{
  const float* x  =(const float*)d_in[0];
  const int* lens =(const int*)d_in[1];
  const float* Wq =(const float*)d_in[2];  const float* bq =(const float*)d_in[3];
  const float* Wk =(const float*)d_in[4];  const float* bk =(const float*)d_in[5];
  const float* Wv =(const float*)d_in[6];  const float* bv =(const float*)d_in[7];
  const float* Wo =(const float*)d_in[8];  const float* bo =(const float*)d_in[9];
  const float* W1 =(const float*)d_in[10]; const float* b1 =(const float*)d_in[11];
  const float* W2 =(const float*)d_in[12]; const float* b2 =(const float*)d_in[13];
  const float* g1 =(const float*)d_in[14]; const float* be1=(const float*)d_in[15];
  const float* g2 =(const float*)d_in[16]; const float* be2=(const float*)d_in[17];

  float* sc=nullptr;
  cudaGetSymbolAddress((void**)&sc, g_scratch);
  float *xb=sc+XBUF, *tb=sc+TBUF, *yb=sc+YBUF;
  hf *qh=(hf*)(sc+QHo), *kh=(hf*)(sc+KHo), *vth=(hf*)(sc+VTHo);
  hf *abh=(hf*)(sc+ABHo), *xh=(hf*)(sc+XHo), *yh=(hf*)(sc+YHo), *fh=(hf*)(sc+FHo);
  hf *wqh=(hf*)(sc+WQo), *wkh=(hf*)(sc+WKo), *wvh=(hf*)(sc+WVo), *woh=(hf*)(sc+WOo);
  hf *w1h=(hf*)(sc+W1o), *w2h=(hf*)(sc+W2o);

  cudaFuncSetAttribute(gemm_std_kernel<0>, cudaFuncAttributeMaxDynamicSharedMemorySize, GEMM_SMEM);
  cudaFuncSetAttribute(gemm_std_kernel<1>, cudaFuncAttributeMaxDynamicSharedMemorySize, GEMM_SMEM);
  cudaFuncSetAttribute(gemm_std_kernel<2>, cudaFuncAttributeMaxDynamicSharedMemorySize, GEMM_SMEM);
  cudaFuncSetAttribute(gemm_qkv_kernel, cudaFuncAttributeMaxDynamicSharedMemorySize, GEMM_SMEM);
  cudaFuncSetAttribute(flash_kernel, cudaFuncAttributeMaxDynamicSharedMemorySize, FLASH_SMEM);

  dim3 wb(32,8);
  wsplit_proj_kernel<<<dim3(16,16,16), wb>>>(Wq,Wk,Wv,Wo, wqh,wkh,wvh,woh);
  wsplit_ff_kernel<<<dim3(64,16,8), wb>>>(W1,W2, w1h,w2h);
  posenc_kernel<<<(Nz*Dz)/256, 256>>>(x, xb, xh);

  dim3 gqkv(12, Nz/128);
  dim3 gproj(Dz/128, Nz/128);
  dim3 gff1(FFz/128, Nz/128);

  for (int l=0;l<Lz;l++){
    size_t wp=(size_t)l*Dz*Dz, wf=(size_t)l*Dz*FFz;
    gemm_qkv_kernel<<<gqkv,128,GEMM_SMEM>>>(xh,
      wqh+wp, wkh+wp, wvh+wp, bq+l*Dz, bk+l*Dz, bv+l*Dz,
      qh, kh, vth);

    flash_kernel<<<dim3(Sz/128, Bz*Hz),256,FLASH_SMEM>>>(qh,kh,vth,lens,abh);

    gemm_std_kernel<0><<<gproj,128,GEMM_SMEM>>>(abh, woh+wp, bo+l*Dz, tb, nullptr, Dz,Dz);
    ln_kernel<true><<<Nz,256>>>(xb,tb,g1+l*Dz,be1+l*Dz, yb,yh);

    gemm_std_kernel<1><<<gff1,128,GEMM_SMEM>>>(yh, w1h+wf, b1+(size_t)l*FFz, nullptr, fh, Dz,FFz);
    gemm_std_kernel<0><<<gproj,128,GEMM_SMEM>>>(fh, w2h+wf, b2+l*Dz, tb, nullptr, FFz,Dz);

    if (l==Lz-1)
      ln_kernel<false><<<Nz,256>>>(yb,tb,g2+l*Dz,be2+l*Dz,(float*)d_out,nullptr);
    else
      ln_kernel<true><<<Nz,256>>>(yb,tb,g2+l*Dz,be2+l*Dz, xb,xh);
  }
}